// round 9
// baseline (speedup 1.0000x reference)
#include <cuda_runtime.h>
#include <cuda_bf16.h>
#include <math.h>
#include <stdint.h>

// ---------------- problem constants ----------------
#define BB     16
#define CC     128
#define TT     294
#define VV     25
#define NTOK   (BB*TT*VV)        // 117600 tokens
#define INNER  512
#define NHEAD  8
#define DH     64
#define PP     7
#define NTP    42                 // T / P
#define NKTOK  (BB*NTP*VV)        // 16800 kv tokens (global)
#define SCALE_ATT 0.125f
#define LN_EPS 1e-5f

// transposed bf16 weight layout (elements, per layer)
#define OFF_LQKV  0               // [1536,128]
#define OFF_LWO   196608          // [128,512]
#define OFF_F1A   262144          // [512,128]
#define OFF_F1B   327680          // [128,512]
#define OFF_GWQ   393216          // [512,128]
#define OFF_GWKV  458752          // [1024,896] (k reordered kp*128+c)
#define OFF_GWO   1376256         // [128,512]
#define OFF_F2A   1441792         // [512,128]
#define OFF_F2B   1507328         // [128,512]
#define WT_LSZ    1572864

// ---------------- scratch (static device memory; no allocs) ----------------
__device__ __align__(16) float          g_xT[NTOK*CC];          // residual, fp32
__device__ __align__(16) __nv_bfloat16  g_xn[NTOK*CC];          // LN output
__device__ __align__(16) __nv_bfloat16  g_qkv[(size_t)NTOK*1536];
__device__ __align__(16) __nv_bfloat16  g_q [NTOK*INNER];
__device__ __align__(16) __nv_bfloat16  g_kv[NKTOK*1024];
__device__ __align__(16) __nv_bfloat16  g_ao[NTOK*INNER];       // attn out / ff hidden
__device__ __align__(16) __nv_bfloat16  g_wt[2*WT_LSZ];

// ---------------- helpers ----------------
__device__ __forceinline__ uint32_t smem_u32(const void* p) {
    uint32_t a;
    asm("{ .reg .u64 t; cvta.to.shared.u64 t, %1; cvt.u32.u64 %0, t; }" : "=r"(a) : "l"(p));
    return a;
}
__device__ __forceinline__ float2 ldbf2(const __nv_bfloat16* p) {
    return __bfloat1622float2(*reinterpret_cast<const __nv_bfloat162*>(p));
}
__device__ __forceinline__ void stbf2(__nv_bfloat16* p, float2 v) {
    *reinterpret_cast<__nv_bfloat162*>(p) = __float22bfloat162_rn(v);
}
__device__ __forceinline__ float2 u2f2(uint32_t u) {
    return __bfloat1622float2(*reinterpret_cast<const __nv_bfloat162*>(&u));
}
__device__ __forceinline__ void mma_bf16(float* d, const uint32_t* a, const uint32_t* b) {
    asm volatile(
        "mma.sync.aligned.m16n8k16.row.col.f32.bf16.bf16.f32 "
        "{%0,%1,%2,%3}, {%4,%5,%6,%7}, {%8,%9}, {%0,%1,%2,%3};"
        : "+f"(d[0]), "+f"(d[1]), "+f"(d[2]), "+f"(d[3])
        : "r"(a[0]), "r"(a[1]), "r"(a[2]), "r"(a[3]), "r"(b[0]), "r"(b[1]));
}
__device__ __forceinline__ float gelu_exact(float v) {
    return 0.5f * v * (1.0f + erff(v * 0.7071067811865475f));
}

// ---------------- transpose in + fused LN(layer0,ln1) ----------------------
__global__ void k_tin(const float* __restrict__ x,
                      const float* __restrict__ gam, const float* __restrict__ bet) {
    int bt = blockIdx.x;
    int t = bt % TT, b = bt / TT;
    __shared__ float sm[CC*VV];
    for (int idx = threadIdx.x; idx < CC*VV; idx += blockDim.x) {
        int c = idx / VV, v = idx % VV;
        sm[idx] = x[(((size_t)b*CC + c)*TT + t)*VV + v];
    }
    __syncthreads();
    size_t base = ((size_t)(b*TT + t))*VV*CC;
    for (int idx = threadIdx.x; idx < CC*VV; idx += blockDim.x) {
        int v = idx / CC, c = idx % CC;
        g_xT[base + idx] = sm[c*VV + v];
    }
    int wid = threadIdx.x >> 5, lane = threadIdx.x & 31;
    int c0 = lane * 4;
    float4 gg = *(const float4*)(gam + c0);
    float4 bb = *(const float4*)(bet + c0);
    for (int v = wid; v < VV; v += 8) {
        float f0 = sm[(c0+0)*VV + v], f1 = sm[(c0+1)*VV + v];
        float f2 = sm[(c0+2)*VV + v], f3 = sm[(c0+3)*VV + v];
        float s = f0+f1+f2+f3, ss = f0*f0+f1*f1+f2*f2+f3*f3;
        #pragma unroll
        for (int o = 16; o; o >>= 1) {
            s  += __shfl_xor_sync(0xffffffffu, s,  o);
            ss += __shfl_xor_sync(0xffffffffu, ss, o);
        }
        float m = s*(1.f/128.f), var = ss*(1.f/128.f) - m*m;
        float r = rsqrtf(var + LN_EPS);
        __nv_bfloat16* dst = g_xn + base + (size_t)v*CC + c0;
        stbf2(dst,     make_float2((f0-m)*r*gg.x + bb.x, (f1-m)*r*gg.y + bb.y));
        stbf2(dst + 2, make_float2((f2-m)*r*gg.z + bb.z, (f3-m)*r*gg.w + bb.w));
    }
}

__global__ void k_tout(float* __restrict__ out) {
    int bt = blockIdx.x;
    int t = bt % TT, b = bt / TT;
    __shared__ float sm[CC*VV];
    size_t base = ((size_t)(b*TT + t))*VV*CC;
    for (int idx = threadIdx.x; idx < CC*VV; idx += blockDim.x)
        sm[idx] = g_xT[base + idx];
    __syncthreads();
    for (int idx = threadIdx.x; idx < CC*VV; idx += blockDim.x) {
        int c = idx / VV, v = idx % VV;
        out[(((size_t)b*CC + c)*TT + t)*VV + v] = sm[v*CC + c];
    }
}

// ---------------- weight prep: one launch per layer ------------------------
__global__ void k_wprep(const float* __restrict__ wq,  const float* __restrict__ wkv,
                        const float* __restrict__ wo,  const float* __restrict__ f1a,
                        const float* __restrict__ f1b, const float* __restrict__ gwq,
                        const float* __restrict__ gwkv,const float* __restrict__ gwo,
                        const float* __restrict__ f2a, const float* __restrict__ f2b,
                        __nv_bfloat16* __restrict__ dst)
{
    for (int idx = blockIdx.x*256 + threadIdx.x; idx < WT_LSZ; idx += gridDim.x*256) {
        float v;
        if (idx < OFF_LWO) {
            int m = idx >> 7, k = idx & 127;
            v = (m < 512) ? wq[k*512 + m] : wkv[k*1024 + (m-512)];
        } else if (idx < OFF_F1A) {
            int r = idx - OFF_LWO; int m = r >> 9, k = r & 511; v = wo[k*128 + m];
        } else if (idx < OFF_F1B) {
            int r = idx - OFF_F1A; int m = r >> 7, k = r & 127; v = f1a[k*512 + m];
        } else if (idx < OFF_GWQ) {
            int r = idx - OFF_F1B; int m = r >> 9, k = r & 511; v = f1b[k*128 + m];
        } else if (idx < OFF_GWKV) {
            int r = idx - OFF_GWQ; int m = r >> 7, k = r & 127; v = gwq[k*512 + m];
        } else if (idx < OFF_GWO) {
            int r = idx - OFF_GWKV; int i = r / 896; int kk = r - i*896;
            int kp = kk >> 7, c = kk & 127;
            v = gwkv[(c*PP + kp)*1024 + i];
        } else if (idx < OFF_F2A) {
            int r = idx - OFF_GWO; int m = r >> 9, k = r & 511; v = gwo[k*128 + m];
        } else if (idx < OFF_F2B) {
            int r = idx - OFF_F2A; int m = r >> 7, k = r & 127; v = f2a[k*512 + m];
        } else {
            int r = idx - OFF_F2B; int m = r >> 9, k = r & 511; v = f2b[k*128 + m];
        }
        dst[idx] = __float2bfloat16(v);
    }
}

// ---------------- channel layernorm: fp32 in, bf16 out ----------------
__global__ void __launch_bounds__(256) k_ln(const float* __restrict__ gam,
                                            const float* __restrict__ bet) {
    int n = blockIdx.x * 8 + (threadIdx.x >> 5);
    if (n >= NTOK) return;
    int lane = threadIdx.x & 31;
    float4 a = ((const float4*)(g_xT + (size_t)n*CC))[lane];
    float s  = a.x + a.y + a.z + a.w;
    float ss = a.x*a.x + a.y*a.y + a.z*a.z + a.w*a.w;
    #pragma unroll
    for (int o = 16; o; o >>= 1) {
        s  += __shfl_xor_sync(0xffffffffu, s,  o);
        ss += __shfl_xor_sync(0xffffffffu, ss, o);
    }
    float m   = s * (1.f/128.f);
    float var = ss * (1.f/128.f) - m*m;
    float r   = rsqrtf(var + LN_EPS);
    float4 gg = ((const float4*)gam)[lane];
    float4 bb = ((const float4*)bet)[lane];
    float2 p0 = make_float2((a.x - m)*r*gg.x + bb.x, (a.y - m)*r*gg.y + bb.y);
    float2 p1 = make_float2((a.z - m)*r*gg.z + bb.z, (a.w - m)*r*gg.w + bb.w);
    uint2 st;
    __nv_bfloat162 h0 = __float22bfloat162_rn(p0);
    __nv_bfloat162 h1 = __float22bfloat162_rn(p1);
    st.x = *reinterpret_cast<uint32_t*>(&h0);
    st.y = *reinterpret_cast<uint32_t*>(&h1);
    *reinterpret_cast<uint2*>(g_xn + (size_t)n*CC + lane*4) = st;
}

// ============================================================================
// bf16 mma GEMM, 64x64 warp tile: C[N,M] = A[N,K] @ Wt[M,K]^T
//   TM x TN CTA tile: (128,256) wide or (256,128) tall; 8 warps (TM/64 x TN/64)
//   K-tile 32, 4-stage cp.async ring (96KB), ldmatrix fragments,
//   swizzled 64B rows (chunk ^= (row>>1)&3). 1 CTA/SM.
//   EPI: 0 none (bf16), 2 bias+gelu (bf16), 3 bias+residual (fp32)
//   GATHER: A rows gathered from g_xn layout (global-kv, K=896, kp=kt>>2)
// ============================================================================
#define W_SMEM 98304

template<int TM, int TN, int EPI, bool GATHER>
__global__ void __launch_bounds__(256, 1) k_gemm_w(
    const __nv_bfloat16* __restrict__ A, const __nv_bfloat16* __restrict__ Wt,
    const float* __restrict__ bias, const float* __restrict__ res,
    void* __restrict__ Cv, int Nrows, int K, int M)
{
    extern __shared__ char smraw[];
    const uint32_t smb = smem_u32(smraw);
    constexpr int SA = TM * 64;           // A stage bytes
    constexpr int SS = (TM + TN) * 64;    // stage stride (24KB)
    constexpr int WR = TM / 64;

    const int t = threadIdx.x;
    const int lane = t & 31, wid = t >> 5;
    const int wr = wid % WR, wc = wid / WR;
    const int rowBase = blockIdx.y * TM, colBase = blockIdx.x * TN;

    // ---- A staging constants
    int aRL, aHalf = 0;
    if (TM == 128) { aRL = t >> 1; aHalf = t & 1; } else { aRL = t; }
    const int aFL = (aRL >> 1) & 3;
    int gaA = rowBase + aRL; if (gaA >= Nrows) gaA = Nrows - 1;
    const __nv_bfloat16* aP = A + (size_t)gaA * K + (aHalf << 4);
    const __nv_bfloat16* gBase = A;
    if (GATHER) {
        int v  = gaA % VV;
        int rr = gaA / VV;
        int tt = rr % NTP;
        int b  = rr / NTP;
        gBase = A + (size_t)(((b*TT + tt*PP)*VV + v))*CC + (aHalf << 4);
    }
    const uint32_t dA0 = (uint32_t)(aRL*64 + 16*((2*aHalf) ^ aFL));

    // ---- B staging constants
    int bRL, bHalf = 0;
    if (TN == 256) { bRL = t; } else { bRL = t >> 1; bHalf = t & 1; }
    const int bFL = (bRL >> 1) & 3;
    const __nv_bfloat16* bP = Wt + (size_t)(colBase + bRL) * K + (bHalf << 4);
    const uint32_t dB0 = (uint32_t)(bRL*64 + 16*((2*bHalf) ^ bFL));

    // ---- ldmatrix lane addressing
    const int rA  = (lane & 7) + ((lane >> 3) & 1) * 8;
    const int ca  = lane >> 4;
    const int fra = (rA >> 1) & 3;
    const int g   = lane >> 3;
    const int nB  = ((g >> 1) & 1) * 8 + (lane & 7);
    const int cb  = g & 1;
    const int fnb = (nB >> 1) & 3;

    float acc[4][8][4];
    #pragma unroll
    for (int mt = 0; mt < 4; ++mt)
        #pragma unroll
        for (int nt = 0; nt < 8; ++nt)
            #pragma unroll
            for (int e = 0; e < 4; ++e) acc[mt][nt][e] = 0.f;

    const int nk = K >> 5;   // >= 4

    #define W_ISSUE(kt_) do {                                                        \
        const uint32_t st_ = smb + (uint32_t)((kt_) & 3) * SS;                        \
        /* ---- A ---- */                                                             \
        if (TM == 128) {                                                              \
            const __nv_bfloat16* asrc_ = GATHER                                       \
                ? (gBase + ((kt_) >> 2)*(VV*CC) + (((kt_) & 3) << 5))                 \
                : (aP + ((kt_) << 5));                                                \
            size_t sa_ = __cvta_generic_to_global(asrc_);                             \
            uint32_t a1_ = st_ + dA0;                                                 \
            asm volatile("cp.async.cg.shared.global [%0], [%1], 16;" :: "r"(a1_), "l"(sa_)); \
            asm volatile("cp.async.cg.shared.global [%0], [%1], 16;" :: "r"(a1_ ^ 16u), "l"(sa_ + 16)); \
        } else {                                                                      \
            size_t sa_ = __cvta_generic_to_global(aP + ((kt_) << 5));                 \
            _Pragma("unroll")                                                         \
            for (int c_ = 0; c_ < 4; ++c_) {                                          \
                uint32_t ad_ = st_ + (uint32_t)(aRL*64 + 16*(c_ ^ aFL));              \
                asm volatile("cp.async.cg.shared.global [%0], [%1], 16;" :: "r"(ad_), "l"(sa_ + c_*16)); \
            }                                                                         \
        }                                                                             \
        /* ---- B ---- */                                                             \
        if (TN == 256) {                                                              \
            size_t sb_ = __cvta_generic_to_global(bP + ((kt_) << 5));                 \
            _Pragma("unroll")                                                         \
            for (int c_ = 0; c_ < 4; ++c_) {                                          \
                uint32_t bd_ = st_ + (uint32_t)SA + (uint32_t)(bRL*64 + 16*(c_ ^ bFL)); \
                asm volatile("cp.async.cg.shared.global [%0], [%1], 16;" :: "r"(bd_), "l"(sb_ + c_*16)); \
            }                                                                         \
        } else {                                                                      \
            size_t sb_ = __cvta_generic_to_global(bP + ((kt_) << 5));                 \
            uint32_t b1_ = st_ + (uint32_t)SA + dB0;                                  \
            asm volatile("cp.async.cg.shared.global [%0], [%1], 16;" :: "r"(b1_), "l"(sb_)); \
            asm volatile("cp.async.cg.shared.global [%0], [%1], 16;" :: "r"(b1_ ^ 16u), "l"(sb_ + 16)); \
        }                                                                             \
    } while (0)

    W_ISSUE(0); asm volatile("cp.async.commit_group;");
    W_ISSUE(1); asm volatile("cp.async.commit_group;");
    W_ISSUE(2); asm volatile("cp.async.commit_group;");

    for (int kt = 0; kt < nk; ++kt) {
        asm volatile("cp.async.wait_group 2;");
        __syncthreads();
        if (kt + 3 < nk) W_ISSUE(kt + 3);
        asm volatile("cp.async.commit_group;");

        const uint32_t stA = smb + (uint32_t)(kt & 3) * SS;
        const uint32_t stB = stA + (uint32_t)SA;
        #pragma unroll
        for (int ks = 0; ks < 2; ++ks) {
            uint32_t af[4][4], bf[8][2];
            #pragma unroll
            for (int mt = 0; mt < 4; ++mt) {
                uint32_t addr = stA + (uint32_t)((wr*64 + mt*16 + rA)*64)
                              + 16u*(uint32_t)(((ks<<1) + ca) ^ fra);
                asm volatile("ldmatrix.sync.aligned.m8n8.x4.shared.b16 {%0,%1,%2,%3}, [%4];"
                    : "=r"(af[mt][0]), "=r"(af[mt][1]), "=r"(af[mt][2]), "=r"(af[mt][3])
                    : "r"(addr));
            }
            #pragma unroll
            for (int j = 0; j < 4; ++j) {
                int n = wc*64 + j*16 + nB;
                uint32_t addr = stB + (uint32_t)(n*64)
                              + 16u*(uint32_t)(((ks<<1) + cb) ^ fnb);
                asm volatile("ldmatrix.sync.aligned.m8n8.x4.shared.b16 {%0,%1,%2,%3}, [%4];"
                    : "=r"(bf[2*j][0]), "=r"(bf[2*j][1]), "=r"(bf[2*j+1][0]), "=r"(bf[2*j+1][1])
                    : "r"(addr));
            }
            #pragma unroll
            for (int mt = 0; mt < 4; ++mt)
                #pragma unroll
                for (int nt = 0; nt < 8; ++nt)
                    mma_bf16(acc[mt][nt], af[mt], bf[nt]);
        }
    }
    #undef W_ISSUE

    // ---------------- epilogue ----------------
    #pragma unroll
    for (int nt = 0; nt < 8; ++nt) {
        const int col = colBase + wc*64 + nt*8 + (lane & 3)*2;
        float2 bb = make_float2(0.f, 0.f);
        if (EPI >= 1) bb = *(const float2*)(bias + col);
        #pragma unroll
        for (int mt = 0; mt < 4; ++mt) {
            #pragma unroll
            for (int hf = 0; hf < 2; ++hf) {
                const int r = rowBase + wr*64 + mt*16 + (lane >> 2) + hf*8;
                if (r >= Nrows) continue;
                float2 o = make_float2(acc[mt][nt][hf*2+0] + bb.x,
                                       acc[mt][nt][hf*2+1] + bb.y);
                if (EPI == 2) { o.x = gelu_exact(o.x); o.y = gelu_exact(o.y); }
                if (EPI == 3) {
                    float2 rv = *(const float2*)(res + (size_t)r*M + col);
                    o.x += rv.x; o.y += rv.y;
                    *(float2*)((float*)Cv + (size_t)r*M + col) = o;
                } else {
                    stbf2((__nv_bfloat16*)Cv + (size_t)r*M + col, o);
                }
            }
        }
    }
}

// ---------------- local attention: one warp per (b, patch, v, head) --------
__global__ void __launch_bounds__(256) k_lattn() {
    int w = blockIdx.x * 8 + (threadIdx.x >> 5);
    int lane = threadIdx.x & 31;
    int h = w & 7;
    int g = w >> 3;
    int v = g % VV;
    int r = g / VV;
    int tt = r % NTP;
    int b = r / NTP;
    int d0 = lane * 2;

    float2 q[PP], kk[PP], vv[PP];
    #pragma unroll
    for (int p = 0; p < PP; ++p) {
        int n = (b*TT + tt*PP + p)*VV + v;
        const __nv_bfloat16* rowp = g_qkv + (size_t)n*1536 + h*DH + d0;
        q[p]  = ldbf2(rowp);
        kk[p] = ldbf2(rowp + 512);
        vv[p] = ldbf2(rowp + 1024);
    }
    float dots[PP][PP];
    #pragma unroll
    for (int i = 0; i < PP; ++i)
        #pragma unroll
        for (int j = 0; j < PP; ++j)
            dots[i][j] = q[i].x*kk[j].x + q[i].y*kk[j].y;
    #pragma unroll
    for (int o = 16; o; o >>= 1)
        #pragma unroll
        for (int i = 0; i < PP; ++i)
            #pragma unroll
            for (int j = 0; j < PP; ++j)
                dots[i][j] += __shfl_xor_sync(0xffffffffu, dots[i][j], o);
    #pragma unroll
    for (int i = 0; i < PP; ++i) {
        float mx = -1e30f;
        #pragma unroll
        for (int j = 0; j < PP; ++j) {
            dots[i][j] *= SCALE_ATT;
            mx = fmaxf(mx, dots[i][j]);
        }
        float s = 0.f;
        #pragma unroll
        for (int j = 0; j < PP; ++j) { dots[i][j] = __expf(dots[i][j] - mx); s += dots[i][j]; }
        float inv = 1.f / s;
        #pragma unroll
        for (int j = 0; j < PP; ++j) dots[i][j] *= inv;
    }
    #pragma unroll
    for (int i = 0; i < PP; ++i) {
        float2 o = make_float2(0.f, 0.f);
        #pragma unroll
        for (int j = 0; j < PP; ++j) {
            o.x += dots[i][j] * vv[j].x;
            o.y += dots[i][j] * vv[j].y;
        }
        int n = (b*TT + tt*PP + i)*VV + v;
        stbf2(g_ao + (size_t)n*INNER + h*DH + d0, o);
    }
}

// ---------------- global attention: one block per (b, h, v) ----------------
__global__ void __launch_bounds__(160) k_gattn() {
    int bid = blockIdx.x;
    int v = bid % VV;
    int rr = bid / VV;
    int h = rr & 7;
    int b = rr >> 3;
    __shared__ float ks[NTP][DH];
    __shared__ float vs[NTP][DH];
    for (int idx = threadIdx.x; idx < NTP*DH/2; idx += 160) {
        int j = idx >> 5, d2 = idx & 31;
        int nk = (b*NTP + j)*VV + v;
        size_t o = (size_t)nk*1024 + h*DH + d2*2;
        float2 kf = ldbf2(g_kv + o);
        float2 vf = ldbf2(g_kv + o + 512);
        ks[j][d2*2] = kf.x; ks[j][d2*2+1] = kf.y;
        vs[j][d2*2] = vf.x; vs[j][d2*2+1] = vf.y;
    }
    __syncthreads();
    int tid = threadIdx.x;
    if (tid >= 147) return;
    int i0 = 2*tid;
    size_t q0 = (size_t)((b*TT + i0)*VV + v)*INNER + h*DH;
    size_t q1 = q0 + (size_t)VV*INNER;

    float da[NTP], db[NTP];
    #pragma unroll
    for (int j = 0; j < NTP; ++j) { da[j] = 0.f; db[j] = 0.f; }

    for (int dchunk = 0; dchunk < 4; ++dchunk) {
        int dbase = dchunk * 16;
        float qa[16], qb[16];
        {
            uint4 u0 = *(const uint4*)(g_q + q0 + dbase);
            uint4 u1 = *(const uint4*)(g_q + q0 + dbase + 8);
            uint4 w0 = *(const uint4*)(g_q + q1 + dbase);
            uint4 w1 = *(const uint4*)(g_q + q1 + dbase + 8);
            float2 f;
            f=u2f2(u0.x); qa[0]=f.x; qa[1]=f.y;  f=u2f2(u0.y); qa[2]=f.x; qa[3]=f.y;
            f=u2f2(u0.z); qa[4]=f.x; qa[5]=f.y;  f=u2f2(u0.w); qa[6]=f.x; qa[7]=f.y;
            f=u2f2(u1.x); qa[8]=f.x; qa[9]=f.y;  f=u2f2(u1.y); qa[10]=f.x; qa[11]=f.y;
            f=u2f2(u1.z); qa[12]=f.x; qa[13]=f.y; f=u2f2(u1.w); qa[14]=f.x; qa[15]=f.y;
            f=u2f2(w0.x); qb[0]=f.x; qb[1]=f.y;  f=u2f2(w0.y); qb[2]=f.x; qb[3]=f.y;
            f=u2f2(w0.z); qb[4]=f.x; qb[5]=f.y;  f=u2f2(w0.w); qb[6]=f.x; qb[7]=f.y;
            f=u2f2(w1.x); qb[8]=f.x; qb[9]=f.y;  f=u2f2(w1.y); qb[10]=f.x; qb[11]=f.y;
            f=u2f2(w1.z); qb[12]=f.x; qb[13]=f.y; f=u2f2(w1.w); qb[14]=f.x; qb[15]=f.y;
        }
        #pragma unroll
        for (int j = 0; j < NTP; ++j) {
            #pragma unroll
            for (int dd = 0; dd < 16; ++dd) {
                float kv = ks[j][dbase + dd];
                da[j] += qa[dd] * kv;
                db[j] += qb[dd] * kv;
            }
        }
    }
    {
        float mx = -1e30f;
        #pragma unroll
        for (int j = 0; j < NTP; ++j) { da[j] *= SCALE_ATT; mx = fmaxf(mx, da[j]); }
        float s = 0.f;
        #pragma unroll
        for (int j = 0; j < NTP; ++j) { da[j] = __expf(da[j] - mx); s += da[j]; }
        float inv = 1.f / s;
        #pragma unroll
        for (int j = 0; j < NTP; ++j) da[j] *= inv;
    }
    {
        float mx = -1e30f;
        #pragma unroll
        for (int j = 0; j < NTP; ++j) { db[j] *= SCALE_ATT; mx = fmaxf(mx, db[j]); }
        float s = 0.f;
        #pragma unroll
        for (int j = 0; j < NTP; ++j) { db[j] = __expf(db[j] - mx); s += db[j]; }
        float inv = 1.f / s;
        #pragma unroll
        for (int j = 0; j < NTP; ++j) db[j] *= inv;
    }
    size_t o0 = q0, o1 = q1;
    for (int dchunk = 0; dchunk < 4; ++dchunk) {
        int dbase = dchunk * 16;
        float oa[16], ob[16];
        #pragma unroll
        for (int dd = 0; dd < 16; ++dd) { oa[dd] = 0.f; ob[dd] = 0.f; }
        #pragma unroll
        for (int j = 0; j < NTP; ++j) {
            #pragma unroll
            for (int dd = 0; dd < 16; ++dd) {
                float vv = vs[j][dbase + dd];
                oa[dd] += da[j] * vv;
                ob[dd] += db[j] * vv;
            }
        }
        #pragma unroll
        for (int dd = 0; dd < 16; dd += 2) {
            stbf2(g_ao + o0 + dbase + dd, make_float2(oa[dd], oa[dd+1]));
            stbf2(g_ao + o1 + dbase + dd, make_float2(ob[dd], ob[dd+1]));
        }
    }
}

// ---------------- launch -----------------------------------------------------
extern "C" void kernel_launch(void* const* d_in, const int* in_sizes, int n_in,
                              void* d_out, int out_size) {
    (void)in_sizes; (void)n_in; (void)out_size;
    float* p_xT;
    __nv_bfloat16 *p_xn, *p_qkv, *p_q, *p_kv, *p_ao, *p_wt;
    cudaGetSymbolAddress((void**)&p_xT,  g_xT);
    cudaGetSymbolAddress((void**)&p_xn,  g_xn);
    cudaGetSymbolAddress((void**)&p_qkv, g_qkv);
    cudaGetSymbolAddress((void**)&p_q,   g_q);
    cudaGetSymbolAddress((void**)&p_kv,  g_kv);
    cudaGetSymbolAddress((void**)&p_ao,  g_ao);
    cudaGetSymbolAddress((void**)&p_wt,  g_wt);

    cudaFuncSetAttribute((k_gemm_w<128,256,0,false>), cudaFuncAttributeMaxDynamicSharedMemorySize, W_SMEM);
    cudaFuncSetAttribute((k_gemm_w<128,256,2,false>), cudaFuncAttributeMaxDynamicSharedMemorySize, W_SMEM);
    cudaFuncSetAttribute((k_gemm_w<128,256,0,true>),  cudaFuncAttributeMaxDynamicSharedMemorySize, W_SMEM);
    cudaFuncSetAttribute((k_gemm_w<256,128,3,false>), cudaFuncAttributeMaxDynamicSharedMemorySize, W_SMEM);

    const float* x      = (const float*)d_in[0];
    const float* ln1_g  = (const float*)d_in[1];
    const float* ln1_b  = (const float*)d_in[2];
    const float* la_wq  = (const float*)d_in[3];
    const float* la_wkv = (const float*)d_in[4];
    const float* la_wo  = (const float*)d_in[5];
    const float* la_bo  = (const float*)d_in[6];
    const float* ln2_g  = (const float*)d_in[7];
    const float* ln2_b  = (const float*)d_in[8];
    const float* ff1_w1 = (const float*)d_in[9];
    const float* ff1_b1 = (const float*)d_in[10];
    const float* ff1_w2 = (const float*)d_in[11];
    const float* ff1_b2 = (const float*)d_in[12];
    const float* ln3_g  = (const float*)d_in[13];
    const float* ln3_b  = (const float*)d_in[14];
    const float* ga_wq  = (const float*)d_in[15];
    const float* ga_wkv = (const float*)d_in[16];
    const float* ga_wo  = (const float*)d_in[17];
    const float* ga_bo  = (const float*)d_in[18];
    const float* ln4_g  = (const float*)d_in[19];
    const float* ln4_b  = (const float*)d_in[20];
    const float* ff2_w1 = (const float*)d_in[21];
    const float* ff2_b1 = (const float*)d_in[22];
    const float* ff2_w2 = (const float*)d_in[23];
    const float* ff2_b2 = (const float*)d_in[24];

    for (int l = 0; l < 2; ++l) {
        k_wprep<<<4096, 256>>>(
            la_wq  + (size_t)l*CC*INNER,      la_wkv + (size_t)l*CC*2*INNER,
            la_wo  + (size_t)l*INNER*CC,      ff1_w1 + (size_t)l*CC*512,
            ff1_w2 + (size_t)l*512*CC,        ga_wq  + (size_t)l*CC*INNER,
            ga_wkv + (size_t)l*CC*PP*2*INNER, ga_wo  + (size_t)l*INNER*CC,
            ff2_w1 + (size_t)l*CC*512,        ff2_w2 + (size_t)l*512*CC,
            p_wt + (size_t)l*WT_LSZ);
    }

    const int rT128  = (NTOK  + 127) / 128;   // 919
    const int rT256  = (NTOK  + 255) / 256;   // 460
    const int rT128G = (NKTOK + 127) / 128;   // 132
    const int lnGrid = NTOK / 8;

    k_tin<<<BB*TT, 256>>>(x, ln1_g, ln1_b);

    for (int l = 0; l < 2; ++l) {
        __nv_bfloat16* wb = p_wt + (size_t)l*WT_LSZ;
        // --- local attention block ---
        k_gemm_w<128,256,0,false><<<dim3(6, rT128), 256, W_SMEM>>>(
            p_xn, wb + OFF_LQKV, nullptr, nullptr, p_qkv, NTOK, 128, 1536);
        k_lattn<<<NKTOK, 256>>>();
        k_gemm_w<256,128,3,false><<<dim3(1, rT256), 256, W_SMEM>>>(
            p_ao, wb + OFF_LWO, la_bo + l*CC, p_xT, p_xT, NTOK, 512, 128);
        k_ln<<<lnGrid, 256>>>(ln2_g + l*CC, ln2_b + l*CC);
        // --- ff1 ---
        k_gemm_w<128,256,2,false><<<dim3(2, rT128), 256, W_SMEM>>>(
            p_xn, wb + OFF_F1A, ff1_b1 + l*512, nullptr, p_ao, NTOK, 128, 512);
        k_gemm_w<256,128,3,false><<<dim3(1, rT256), 256, W_SMEM>>>(
            p_ao, wb + OFF_F1B, ff1_b2 + l*CC, p_xT, p_xT, NTOK, 512, 128);
        k_ln<<<lnGrid, 256>>>(ln3_g + l*CC, ln3_b + l*CC);
        // --- global attention block ---
        k_gemm_w<128,256,0,false><<<dim3(2, rT128), 256, W_SMEM>>>(
            p_xn, wb + OFF_GWQ, nullptr, nullptr, p_q, NTOK, 128, 512);
        k_gemm_w<128,256,0,true><<<dim3(4, rT128G), 256, W_SMEM>>>(
            p_xn, wb + OFF_GWKV, nullptr, nullptr, p_kv, NKTOK, 896, 1024);
        k_gattn<<<BB*NHEAD*VV, 160>>>();
        k_gemm_w<256,128,3,false><<<dim3(1, rT256), 256, W_SMEM>>>(
            p_ao, wb + OFF_GWO, ga_bo + l*CC, p_xT, p_xT, NTOK, 512, 128);
        k_ln<<<lnGrid, 256>>>(ln4_g + l*CC, ln4_b + l*CC);
        // --- ff2 ---
        k_gemm_w<128,256,2,false><<<dim3(2, rT128), 256, W_SMEM>>>(
            p_xn, wb + OFF_F2A, ff2_b1 + l*512, nullptr, p_ao, NTOK, 128, 512);
        k_gemm_w<256,128,3,false><<<dim3(1, rT256), 256, W_SMEM>>>(
            p_ao, wb + OFF_F2B, ff2_b2 + l*CC, p_xT, p_xT, NTOK, 512, 128);
        if (l == 0) k_ln<<<lnGrid, 256>>>(ln1_g + CC, ln1_b + CC);
    }
    k_tout<<<BB*TT, 256>>>((float*)d_out);
}

// round 10
// speedup vs baseline: 1.1734x; 1.1734x over previous
#include <cuda_runtime.h>
#include <cuda_bf16.h>
#include <math.h>
#include <stdint.h>

// ---------------- problem constants ----------------
#define BB     16
#define CC     128
#define TT     294
#define VV     25
#define NTOK   (BB*TT*VV)        // 117600 tokens
#define INNER  512
#define NHEAD  8
#define DH     64
#define PP     7
#define NTP    42                 // T / P
#define NKTOK  (BB*NTP*VV)        // 16800 kv tokens (global)
#define SCALE_ATT 0.125f
#define LN_EPS 1e-5f

// transposed bf16 weight layout (elements, per layer)
#define OFF_LQKV  0               // [1536,128]
#define OFF_LWO   196608          // [128,512]
#define OFF_F1A   262144          // [512,128]
#define OFF_F1B   327680          // [128,512]
#define OFF_GWQ   393216          // [512,128]
#define OFF_GWKV  458752          // [1024,896] (k reordered kp*128+c)
#define OFF_GWO   1376256         // [128,512]
#define OFF_F2A   1441792         // [512,128]
#define OFF_F2B   1507328         // [128,512]
#define WT_LSZ    1572864

// ---------------- scratch (static device memory; no allocs) ----------------
__device__ __align__(16) float          g_xT[NTOK*CC];          // residual, fp32
__device__ __align__(16) __nv_bfloat16  g_xn[NTOK*CC];          // LN output
__device__ __align__(16) __nv_bfloat16  g_qkv[(size_t)NTOK*1536];
__device__ __align__(16) __nv_bfloat16  g_q [NTOK*INNER];
__device__ __align__(16) __nv_bfloat16  g_kv[NKTOK*1024];
__device__ __align__(16) __nv_bfloat16  g_ao[NTOK*INNER];       // attn out / ff hidden
__device__ __align__(16) __nv_bfloat16  g_wt[2*WT_LSZ];

// ---------------- helpers ----------------
__device__ __forceinline__ uint32_t smem_u32(const void* p) {
    uint32_t a;
    asm("{ .reg .u64 t; cvta.to.shared.u64 t, %1; cvt.u32.u64 %0, t; }" : "=r"(a) : "l"(p));
    return a;
}
__device__ __forceinline__ float2 ldbf2(const __nv_bfloat16* p) {
    return __bfloat1622float2(*reinterpret_cast<const __nv_bfloat162*>(p));
}
__device__ __forceinline__ void stbf2(__nv_bfloat16* p, float2 v) {
    *reinterpret_cast<__nv_bfloat162*>(p) = __float22bfloat162_rn(v);
}
__device__ __forceinline__ float2 u2f2(uint32_t u) {
    return __bfloat1622float2(*reinterpret_cast<const __nv_bfloat162*>(&u));
}
__device__ __forceinline__ void mma_bf16(float* d, const uint32_t* a, const uint32_t* b) {
    asm volatile(
        "mma.sync.aligned.m16n8k16.row.col.f32.bf16.bf16.f32 "
        "{%0,%1,%2,%3}, {%4,%5,%6,%7}, {%8,%9}, {%0,%1,%2,%3};"
        : "+f"(d[0]), "+f"(d[1]), "+f"(d[2]), "+f"(d[3])
        : "r"(a[0]), "r"(a[1]), "r"(a[2]), "r"(a[3]), "r"(b[0]), "r"(b[1]));
}
__device__ __forceinline__ float gelu_exact(float v) {
    return 0.5f * v * (1.0f + erff(v * 0.7071067811865475f));
}

// ---------------- transpose in + fused LN(layer0,ln1) ----------------------
__global__ void k_tin(const float* __restrict__ x,
                      const float* __restrict__ gam, const float* __restrict__ bet) {
    int bt = blockIdx.x;
    int t = bt % TT, b = bt / TT;
    __shared__ float sm[CC*VV];
    for (int idx = threadIdx.x; idx < CC*VV; idx += blockDim.x) {
        int c = idx / VV, v = idx % VV;
        sm[idx] = x[(((size_t)b*CC + c)*TT + t)*VV + v];
    }
    __syncthreads();
    size_t base = ((size_t)(b*TT + t))*VV*CC;
    for (int idx = threadIdx.x; idx < CC*VV; idx += blockDim.x) {
        int v = idx / CC, c = idx % CC;
        g_xT[base + idx] = sm[c*VV + v];
    }
    int wid = threadIdx.x >> 5, lane = threadIdx.x & 31;
    int c0 = lane * 4;
    float4 gg = *(const float4*)(gam + c0);
    float4 bb = *(const float4*)(bet + c0);
    for (int v = wid; v < VV; v += 8) {
        float f0 = sm[(c0+0)*VV + v], f1 = sm[(c0+1)*VV + v];
        float f2 = sm[(c0+2)*VV + v], f3 = sm[(c0+3)*VV + v];
        float s = f0+f1+f2+f3, ss = f0*f0+f1*f1+f2*f2+f3*f3;
        #pragma unroll
        for (int o = 16; o; o >>= 1) {
            s  += __shfl_xor_sync(0xffffffffu, s,  o);
            ss += __shfl_xor_sync(0xffffffffu, ss, o);
        }
        float m = s*(1.f/128.f), var = ss*(1.f/128.f) - m*m;
        float r = rsqrtf(var + LN_EPS);
        __nv_bfloat16* dst = g_xn + base + (size_t)v*CC + c0;
        stbf2(dst,     make_float2((f0-m)*r*gg.x + bb.x, (f1-m)*r*gg.y + bb.y));
        stbf2(dst + 2, make_float2((f2-m)*r*gg.z + bb.z, (f3-m)*r*gg.w + bb.w));
    }
}

__global__ void k_tout(float* __restrict__ out) {
    int bt = blockIdx.x;
    int t = bt % TT, b = bt / TT;
    __shared__ float sm[CC*VV];
    size_t base = ((size_t)(b*TT + t))*VV*CC;
    for (int idx = threadIdx.x; idx < CC*VV; idx += blockDim.x)
        sm[idx] = g_xT[base + idx];
    __syncthreads();
    for (int idx = threadIdx.x; idx < CC*VV; idx += blockDim.x) {
        int c = idx / VV, v = idx % VV;
        out[(((size_t)b*CC + c)*TT + t)*VV + v] = sm[v*CC + c];
    }
}

// ---------------- weight prep: one launch per layer ------------------------
__global__ void k_wprep(const float* __restrict__ wq,  const float* __restrict__ wkv,
                        const float* __restrict__ wo,  const float* __restrict__ f1a,
                        const float* __restrict__ f1b, const float* __restrict__ gwq,
                        const float* __restrict__ gwkv,const float* __restrict__ gwo,
                        const float* __restrict__ f2a, const float* __restrict__ f2b,
                        __nv_bfloat16* __restrict__ dst)
{
    for (int idx = blockIdx.x*256 + threadIdx.x; idx < WT_LSZ; idx += gridDim.x*256) {
        float v;
        if (idx < OFF_LWO) {
            int m = idx >> 7, k = idx & 127;
            v = (m < 512) ? wq[k*512 + m] : wkv[k*1024 + (m-512)];
        } else if (idx < OFF_F1A) {
            int r = idx - OFF_LWO; int m = r >> 9, k = r & 511; v = wo[k*128 + m];
        } else if (idx < OFF_F1B) {
            int r = idx - OFF_F1A; int m = r >> 7, k = r & 127; v = f1a[k*512 + m];
        } else if (idx < OFF_GWQ) {
            int r = idx - OFF_F1B; int m = r >> 9, k = r & 511; v = f1b[k*128 + m];
        } else if (idx < OFF_GWKV) {
            int r = idx - OFF_GWQ; int m = r >> 7, k = r & 127; v = gwq[k*512 + m];
        } else if (idx < OFF_GWO) {
            int r = idx - OFF_GWKV; int i = r / 896; int kk = r - i*896;
            int kp = kk >> 7, c = kk & 127;
            v = gwkv[(c*PP + kp)*1024 + i];
        } else if (idx < OFF_F2A) {
            int r = idx - OFF_GWO; int m = r >> 9, k = r & 511; v = gwo[k*128 + m];
        } else if (idx < OFF_F2B) {
            int r = idx - OFF_F2A; int m = r >> 7, k = r & 127; v = f2a[k*512 + m];
        } else {
            int r = idx - OFF_F2B; int m = r >> 9, k = r & 511; v = f2b[k*128 + m];
        }
        dst[idx] = __float2bfloat16(v);
    }
}

// ---------------- channel layernorm: fp32 in, bf16 out ----------------
__global__ void __launch_bounds__(256) k_ln(const float* __restrict__ gam,
                                            const float* __restrict__ bet) {
    int n = blockIdx.x * 8 + (threadIdx.x >> 5);
    if (n >= NTOK) return;
    int lane = threadIdx.x & 31;
    float4 a = ((const float4*)(g_xT + (size_t)n*CC))[lane];
    float s  = a.x + a.y + a.z + a.w;
    float ss = a.x*a.x + a.y*a.y + a.z*a.z + a.w*a.w;
    #pragma unroll
    for (int o = 16; o; o >>= 1) {
        s  += __shfl_xor_sync(0xffffffffu, s,  o);
        ss += __shfl_xor_sync(0xffffffffu, ss, o);
    }
    float m   = s * (1.f/128.f);
    float var = ss * (1.f/128.f) - m*m;
    float r   = rsqrtf(var + LN_EPS);
    float4 gg = ((const float4*)gam)[lane];
    float4 bb = ((const float4*)bet)[lane];
    float2 p0 = make_float2((a.x - m)*r*gg.x + bb.x, (a.y - m)*r*gg.y + bb.y);
    float2 p1 = make_float2((a.z - m)*r*gg.z + bb.z, (a.w - m)*r*gg.w + bb.w);
    uint2 st;
    __nv_bfloat162 h0 = __float22bfloat162_rn(p0);
    __nv_bfloat162 h1 = __float22bfloat162_rn(p1);
    st.x = *reinterpret_cast<uint32_t*>(&h0);
    st.y = *reinterpret_cast<uint32_t*>(&h1);
    *reinterpret_cast<uint2*>(g_xn + (size_t)n*CC + lane*4) = st;
}

// ---------------- bf16 mma GEMM: C[N,M] = A[N,K] @ Wt[M,K]^T ---------------
// 128x128 CTA tile, 64x32 warp tile, K-tile 64 (two 32-wide sub-tiles),
// 3-stage cp.async ring (96KB), ldmatrix fragments, swizzled rows. 2 CTAs/SM.
// EPI: 0 none (bf16 out), 2 bias+gelu (bf16 out), 3 bias+residual (fp32 out)
// GATHER: A rows gathered from g_xn layout (global-kv, K=896, kp=kt>>1)
#define GSTAGE_BYTES 32768
#define GEMM_SMEM   (3*GSTAGE_BYTES)

template<int EPI, bool GATHER>
__global__ void __launch_bounds__(256, 2) k_gemm_bf(
    const __nv_bfloat16* __restrict__ A, const __nv_bfloat16* __restrict__ Wt,
    const float* __restrict__ bias, const float* __restrict__ res,
    void* __restrict__ Cv, int Nrows, int K, int M)
{
    extern __shared__ char smraw[];
    const uint32_t smb = smem_u32(smraw);

    const int t = threadIdx.x;
    const int lane = t & 31, wid = t >> 5;
    const int wr = wid & 1, wc = wid >> 1;
    const int rowBase = blockIdx.y << 7, colBase = blockIdx.x << 7;

    // staging: thread owns row rL, 16B chunk `half` within each 32-wide sub-tile
    const int rL = t >> 1, half = t & 1;
    int ga = rowBase + rL; if (ga >= Nrows) ga = Nrows - 1;
    const __nv_bfloat16* aP = A  + (size_t)ga * K + (half << 4);
    const __nv_bfloat16* bP = Wt + (size_t)(colBase + rL) * K + (half << 4);
    const __nv_bfloat16* gBase = A;
    if (GATHER) {
        int v  = ga % VV;
        int rr = ga / VV;
        int tt = rr % NTP;
        int b  = rr / NTP;
        gBase = A + (size_t)(((b*TT + tt*PP)*VV + v))*CC + (half << 4);
    }
    const int fL = (rL >> 1) & 3;
    const uint32_t dA = rL*64 + 16*((2*half) ^ fL);   // within 8KB sub-tile
    const uint32_t dB = 16384 + dA;

    // ldmatrix lane addressing
    const int rA  = (lane & 7) + ((lane >> 3) & 1) * 8;
    const int ca  = lane >> 4;
    const int fra = (rA >> 1) & 3;
    const int g   = lane >> 3;
    const int nB  = ((g >> 1) & 1) * 8 + (lane & 7);
    const int cb  = g & 1;
    const int fnb = (nB >> 1) & 3;

    float acc[4][4][4];
    #pragma unroll
    for (int mt = 0; mt < 4; ++mt)
        #pragma unroll
        for (int nt = 0; nt < 4; ++nt)
            #pragma unroll
            for (int e = 0; e < 4; ++e) acc[mt][nt][e] = 0.f;

    const int nk = K >> 6;   // k-tiles of 64; K in {128,512,896} => nk in {2,8,14}

    // stage layout: [A sub0 8KB][A sub1 8KB][B sub0 8KB][B sub1 8KB]
    #define G_ISSUE(kt_) do {                                                        \
        const uint32_t st_ = smb + (uint32_t)((kt_) % 3) * GSTAGE_BYTES;              \
        _Pragma("unroll")                                                             \
        for (int sub_ = 0; sub_ < 2; ++sub_) {                                        \
            const __nv_bfloat16* asrc_ = GATHER                                       \
                ? (gBase + ((kt_) >> 1)*(VV*CC) + (((kt_) & 1) << 6) + (sub_ << 5))   \
                : (aP + ((kt_) << 6) + (sub_ << 5));                                  \
            size_t sa_ = __cvta_generic_to_global(asrc_);                             \
            size_t sb_ = __cvta_generic_to_global(bP + ((kt_) << 6) + (sub_ << 5));   \
            uint32_t a1_ = st_ + (uint32_t)(sub_*8192) + dA;                          \
            uint32_t b1_ = st_ + (uint32_t)(sub_*8192) + dB;                          \
            asm volatile("cp.async.cg.shared.global [%0], [%1], 16;" :: "r"(a1_), "l"(sa_)); \
            asm volatile("cp.async.cg.shared.global [%0], [%1], 16;" :: "r"(a1_ ^ 16u), "l"(sa_ + 16)); \
            asm volatile("cp.async.cg.shared.global [%0], [%1], 16;" :: "r"(b1_), "l"(sb_)); \
            asm volatile("cp.async.cg.shared.global [%0], [%1], 16;" :: "r"(b1_ ^ 16u), "l"(sb_ + 16)); \
        }                                                                             \
    } while (0)

    G_ISSUE(0); asm volatile("cp.async.commit_group;");
    G_ISSUE(1); asm volatile("cp.async.commit_group;");

    for (int kt = 0; kt < nk; ++kt) {
        asm volatile("cp.async.wait_group 1;");
        __syncthreads();
        if (kt + 2 < nk) G_ISSUE(kt + 2);
        asm volatile("cp.async.commit_group;");

        const uint32_t st = smb + (uint32_t)(kt % 3) * GSTAGE_BYTES;
        #pragma unroll
        for (int sub = 0; sub < 2; ++sub) {
            const uint32_t stA = st + sub*8192;
            const uint32_t stB = stA + 16384;
            #pragma unroll
            for (int ks = 0; ks < 2; ++ks) {
                uint32_t af[4][4], bf[4][2];
                #pragma unroll
                for (int mt = 0; mt < 4; ++mt) {
                    uint32_t addr = stA + (uint32_t)((wr*64 + mt*16 + rA)*64)
                                  + 16u*(uint32_t)(((ks<<1) + ca) ^ fra);
                    asm volatile("ldmatrix.sync.aligned.m8n8.x4.shared.b16 {%0,%1,%2,%3}, [%4];"
                        : "=r"(af[mt][0]), "=r"(af[mt][1]), "=r"(af[mt][2]), "=r"(af[mt][3])
                        : "r"(addr));
                }
                #pragma unroll
                for (int j = 0; j < 2; ++j) {
                    int n = wc*32 + j*16 + nB;
                    uint32_t addr = stB + (uint32_t)(n*64)
                                  + 16u*(uint32_t)(((ks<<1) + cb) ^ fnb);
                    asm volatile("ldmatrix.sync.aligned.m8n8.x4.shared.b16 {%0,%1,%2,%3}, [%4];"
                        : "=r"(bf[2*j][0]), "=r"(bf[2*j][1]), "=r"(bf[2*j+1][0]), "=r"(bf[2*j+1][1])
                        : "r"(addr));
                }
                #pragma unroll
                for (int mt = 0; mt < 4; ++mt)
                    #pragma unroll
                    for (int nt = 0; nt < 4; ++nt)
                        mma_bf16(acc[mt][nt], af[mt], bf[nt]);
            }
        }
    }
    #undef G_ISSUE

    // ---------------- epilogue ----------------
    #pragma unroll
    for (int nt = 0; nt < 4; ++nt) {
        const int col = colBase + wc*32 + nt*8 + (lane & 3)*2;
        float2 bb = make_float2(0.f, 0.f);
        if (EPI >= 1) bb = *(const float2*)(bias + col);
        #pragma unroll
        for (int mt = 0; mt < 4; ++mt) {
            #pragma unroll
            for (int hf = 0; hf < 2; ++hf) {
                const int r = rowBase + wr*64 + mt*16 + (lane >> 2) + hf*8;
                if (r >= Nrows) continue;
                float2 o = make_float2(acc[mt][nt][hf*2+0] + bb.x,
                                       acc[mt][nt][hf*2+1] + bb.y);
                if (EPI == 2) { o.x = gelu_exact(o.x); o.y = gelu_exact(o.y); }
                if (EPI == 3) {
                    float2 rv = *(const float2*)(res + (size_t)r*M + col);
                    o.x += rv.x; o.y += rv.y;
                    *(float2*)((float*)Cv + (size_t)r*M + col) = o;
                } else {
                    stbf2((__nv_bfloat16*)Cv + (size_t)r*M + col, o);
                }
            }
        }
    }
}

// ---------------- local attention: one warp per (b, patch, v, head) --------
__global__ void __launch_bounds__(256) k_lattn() {
    int w = blockIdx.x * 8 + (threadIdx.x >> 5);
    int lane = threadIdx.x & 31;
    int h = w & 7;
    int g = w >> 3;
    int v = g % VV;
    int r = g / VV;
    int tt = r % NTP;
    int b = r / NTP;
    int d0 = lane * 2;

    float2 q[PP], kk[PP], vv[PP];
    #pragma unroll
    for (int p = 0; p < PP; ++p) {
        int n = (b*TT + tt*PP + p)*VV + v;
        const __nv_bfloat16* rowp = g_qkv + (size_t)n*1536 + h*DH + d0;
        q[p]  = ldbf2(rowp);
        kk[p] = ldbf2(rowp + 512);
        vv[p] = ldbf2(rowp + 1024);
    }
    float dots[PP][PP];
    #pragma unroll
    for (int i = 0; i < PP; ++i)
        #pragma unroll
        for (int j = 0; j < PP; ++j)
            dots[i][j] = q[i].x*kk[j].x + q[i].y*kk[j].y;
    #pragma unroll
    for (int o = 16; o; o >>= 1)
        #pragma unroll
        for (int i = 0; i < PP; ++i)
            #pragma unroll
            for (int j = 0; j < PP; ++j)
                dots[i][j] += __shfl_xor_sync(0xffffffffu, dots[i][j], o);
    #pragma unroll
    for (int i = 0; i < PP; ++i) {
        float mx = -1e30f;
        #pragma unroll
        for (int j = 0; j < PP; ++j) {
            dots[i][j] *= SCALE_ATT;
            mx = fmaxf(mx, dots[i][j]);
        }
        float s = 0.f;
        #pragma unroll
        for (int j = 0; j < PP; ++j) { dots[i][j] = __expf(dots[i][j] - mx); s += dots[i][j]; }
        float inv = 1.f / s;
        #pragma unroll
        for (int j = 0; j < PP; ++j) dots[i][j] *= inv;
    }
    #pragma unroll
    for (int i = 0; i < PP; ++i) {
        float2 o = make_float2(0.f, 0.f);
        #pragma unroll
        for (int j = 0; j < PP; ++j) {
            o.x += dots[i][j] * vv[j].x;
            o.y += dots[i][j] * vv[j].y;
        }
        int n = (b*TT + tt*PP + i)*VV + v;
        stbf2(g_ao + (size_t)n*INNER + h*DH + d0, o);
    }
}

// ---------------- global attention: one block per (b, h, v) ----------------
__global__ void __launch_bounds__(160) k_gattn() {
    int bid = blockIdx.x;
    int v = bid % VV;
    int rr = bid / VV;
    int h = rr & 7;
    int b = rr >> 3;
    __shared__ float ks[NTP][DH];
    __shared__ float vs[NTP][DH];
    for (int idx = threadIdx.x; idx < NTP*DH/2; idx += 160) {
        int j = idx >> 5, d2 = idx & 31;
        int nk = (b*NTP + j)*VV + v;
        size_t o = (size_t)nk*1024 + h*DH + d2*2;
        float2 kf = ldbf2(g_kv + o);
        float2 vf = ldbf2(g_kv + o + 512);
        ks[j][d2*2] = kf.x; ks[j][d2*2+1] = kf.y;
        vs[j][d2*2] = vf.x; vs[j][d2*2+1] = vf.y;
    }
    __syncthreads();
    int tid = threadIdx.x;
    if (tid >= 147) return;
    int i0 = 2*tid;
    size_t q0 = (size_t)((b*TT + i0)*VV + v)*INNER + h*DH;
    size_t q1 = q0 + (size_t)VV*INNER;

    float da[NTP], db[NTP];
    #pragma unroll
    for (int j = 0; j < NTP; ++j) { da[j] = 0.f; db[j] = 0.f; }

    for (int dchunk = 0; dchunk < 4; ++dchunk) {
        int dbase = dchunk * 16;
        float qa[16], qb[16];
        {
            uint4 u0 = *(const uint4*)(g_q + q0 + dbase);
            uint4 u1 = *(const uint4*)(g_q + q0 + dbase + 8);
            uint4 w0 = *(const uint4*)(g_q + q1 + dbase);
            uint4 w1 = *(const uint4*)(g_q + q1 + dbase + 8);
            float2 f;
            f=u2f2(u0.x); qa[0]=f.x; qa[1]=f.y;  f=u2f2(u0.y); qa[2]=f.x; qa[3]=f.y;
            f=u2f2(u0.z); qa[4]=f.x; qa[5]=f.y;  f=u2f2(u0.w); qa[6]=f.x; qa[7]=f.y;
            f=u2f2(u1.x); qa[8]=f.x; qa[9]=f.y;  f=u2f2(u1.y); qa[10]=f.x; qa[11]=f.y;
            f=u2f2(u1.z); qa[12]=f.x; qa[13]=f.y; f=u2f2(u1.w); qa[14]=f.x; qa[15]=f.y;
            f=u2f2(w0.x); qb[0]=f.x; qb[1]=f.y;  f=u2f2(w0.y); qb[2]=f.x; qb[3]=f.y;
            f=u2f2(w0.z); qb[4]=f.x; qb[5]=f.y;  f=u2f2(w0.w); qb[6]=f.x; qb[7]=f.y;
            f=u2f2(w1.x); qb[8]=f.x; qb[9]=f.y;  f=u2f2(w1.y); qb[10]=f.x; qb[11]=f.y;
            f=u2f2(w1.z); qb[12]=f.x; qb[13]=f.y; f=u2f2(w1.w); qb[14]=f.x; qb[15]=f.y;
        }
        #pragma unroll
        for (int j = 0; j < NTP; ++j) {
            #pragma unroll
            for (int dd = 0; dd < 16; ++dd) {
                float kv = ks[j][dbase + dd];
                da[j] += qa[dd] * kv;
                db[j] += qb[dd] * kv;
            }
        }
    }
    {
        float mx = -1e30f;
        #pragma unroll
        for (int j = 0; j < NTP; ++j) { da[j] *= SCALE_ATT; mx = fmaxf(mx, da[j]); }
        float s = 0.f;
        #pragma unroll
        for (int j = 0; j < NTP; ++j) { da[j] = __expf(da[j] - mx); s += da[j]; }
        float inv = 1.f / s;
        #pragma unroll
        for (int j = 0; j < NTP; ++j) da[j] *= inv;
    }
    {
        float mx = -1e30f;
        #pragma unroll
        for (int j = 0; j < NTP; ++j) { db[j] *= SCALE_ATT; mx = fmaxf(mx, db[j]); }
        float s = 0.f;
        #pragma unroll
        for (int j = 0; j < NTP; ++j) { db[j] = __expf(db[j] - mx); s += db[j]; }
        float inv = 1.f / s;
        #pragma unroll
        for (int j = 0; j < NTP; ++j) db[j] *= inv;
    }
    size_t o0 = q0, o1 = q1;
    for (int dchunk = 0; dchunk < 4; ++dchunk) {
        int dbase = dchunk * 16;
        float oa[16], ob[16];
        #pragma unroll
        for (int dd = 0; dd < 16; ++dd) { oa[dd] = 0.f; ob[dd] = 0.f; }
        #pragma unroll
        for (int j = 0; j < NTP; ++j) {
            #pragma unroll
            for (int dd = 0; dd < 16; ++dd) {
                float vv = vs[j][dbase + dd];
                oa[dd] += da[j] * vv;
                ob[dd] += db[j] * vv;
            }
        }
        #pragma unroll
        for (int dd = 0; dd < 16; dd += 2) {
            stbf2(g_ao + o0 + dbase + dd, make_float2(oa[dd], oa[dd+1]));
            stbf2(g_ao + o1 + dbase + dd, make_float2(ob[dd], ob[dd+1]));
        }
    }
}

// ---------------- launch -----------------------------------------------------
extern "C" void kernel_launch(void* const* d_in, const int* in_sizes, int n_in,
                              void* d_out, int out_size) {
    (void)in_sizes; (void)n_in; (void)out_size;
    float* p_xT;
    __nv_bfloat16 *p_xn, *p_qkv, *p_q, *p_kv, *p_ao, *p_wt;
    cudaGetSymbolAddress((void**)&p_xT,  g_xT);
    cudaGetSymbolAddress((void**)&p_xn,  g_xn);
    cudaGetSymbolAddress((void**)&p_qkv, g_qkv);
    cudaGetSymbolAddress((void**)&p_q,   g_q);
    cudaGetSymbolAddress((void**)&p_kv,  g_kv);
    cudaGetSymbolAddress((void**)&p_ao,  g_ao);
    cudaGetSymbolAddress((void**)&p_wt,  g_wt);

    cudaFuncSetAttribute((k_gemm_bf<0,false>), cudaFuncAttributeMaxDynamicSharedMemorySize, GEMM_SMEM);
    cudaFuncSetAttribute((k_gemm_bf<2,false>), cudaFuncAttributeMaxDynamicSharedMemorySize, GEMM_SMEM);
    cudaFuncSetAttribute((k_gemm_bf<3,false>), cudaFuncAttributeMaxDynamicSharedMemorySize, GEMM_SMEM);
    cudaFuncSetAttribute((k_gemm_bf<0,true>),  cudaFuncAttributeMaxDynamicSharedMemorySize, GEMM_SMEM);

    const float* x      = (const float*)d_in[0];
    const float* ln1_g  = (const float*)d_in[1];
    const float* ln1_b  = (const float*)d_in[2];
    const float* la_wq  = (const float*)d_in[3];
    const float* la_wkv = (const float*)d_in[4];
    const float* la_wo  = (const float*)d_in[5];
    const float* la_bo  = (const float*)d_in[6];
    const float* ln2_g  = (const float*)d_in[7];
    const float* ln2_b  = (const float*)d_in[8];
    const float* ff1_w1 = (const float*)d_in[9];
    const float* ff1_b1 = (const float*)d_in[10];
    const float* ff1_w2 = (const float*)d_in[11];
    const float* ff1_b2 = (const float*)d_in[12];
    const float* ln3_g  = (const float*)d_in[13];
    const float* ln3_b  = (const float*)d_in[14];
    const float* ga_wq  = (const float*)d_in[15];
    const float* ga_wkv = (const float*)d_in[16];
    const float* ga_wo  = (const float*)d_in[17];
    const float* ga_bo  = (const float*)d_in[18];
    const float* ln4_g  = (const float*)d_in[19];
    const float* ln4_b  = (const float*)d_in[20];
    const float* ff2_w1 = (const float*)d_in[21];
    const float* ff2_b1 = (const float*)d_in[22];
    const float* ff2_w2 = (const float*)d_in[23];
    const float* ff2_b2 = (const float*)d_in[24];

    for (int l = 0; l < 2; ++l) {
        k_wprep<<<4096, 256>>>(
            la_wq  + (size_t)l*CC*INNER,      la_wkv + (size_t)l*CC*2*INNER,
            la_wo  + (size_t)l*INNER*CC,      ff1_w1 + (size_t)l*CC*512,
            ff1_w2 + (size_t)l*512*CC,        ga_wq  + (size_t)l*CC*INNER,
            ga_wkv + (size_t)l*CC*PP*2*INNER, ga_wo  + (size_t)l*INNER*CC,
            ff2_w1 + (size_t)l*CC*512,        ff2_w2 + (size_t)l*512*CC,
            p_wt + (size_t)l*WT_LSZ);
    }

    const int rowTiles  = (NTOK  + 127) / 128;   // 919
    const int rowTilesG = (NKTOK + 127) / 128;   // 132
    const int lnGrid = NTOK / 8;

    k_tin<<<BB*TT, 256>>>(x, ln1_g, ln1_b);

    for (int l = 0; l < 2; ++l) {
        __nv_bfloat16* wb = p_wt + (size_t)l*WT_LSZ;
        // --- local attention block ---
        k_gemm_bf<0,false><<<dim3(12, rowTiles), 256, GEMM_SMEM>>>(
            p_xn, wb + OFF_LQKV, nullptr, nullptr, p_qkv, NTOK, 128, 1536);
        k_lattn<<<NKTOK, 256>>>();
        k_gemm_bf<3,false><<<dim3(1, rowTiles), 256, GEMM_SMEM>>>(
            p_ao, wb + OFF_LWO, la_bo + l*CC, p_xT, p_xT, NTOK, 512, 128);
        k_ln<<<lnGrid, 256>>>(ln2_g + l*CC, ln2_b + l*CC);
        // --- ff1 ---
        k_gemm_bf<2,false><<<dim3(4, rowTiles), 256, GEMM_SMEM>>>(
            p_xn, wb + OFF_F1A, ff1_b1 + l*512, nullptr, p_ao, NTOK, 128, 512);
        k_gemm_bf<3,false><<<dim3(1, rowTiles), 256, GEMM_SMEM>>>(
            p_ao, wb + OFF_F1B, ff1_b2 + l*CC, p_xT, p_xT, NTOK, 512, 128);
        k_ln<<<lnGrid, 256>>>(ln3_g + l*CC, ln3_b + l*CC);
        // --- global attention block ---
        k_gemm_bf<0,false><<<dim3(4, rowTiles), 256, GEMM_SMEM>>>(
            p_xn, wb + OFF_GWQ, nullptr, nullptr, p_q, NTOK, 128, 512);
        k_gemm_bf<0,true><<<dim3(8, rowTilesG), 256, GEMM_SMEM>>>(
            p_xn, wb + OFF_GWKV, nullptr, nullptr, p_kv, NKTOK, 896, 1024);
        k_gattn<<<BB*NHEAD*VV, 160>>>();
        k_gemm_bf<3,false><<<dim3(1, rowTiles), 256, GEMM_SMEM>>>(
            p_ao, wb + OFF_GWO, ga_bo + l*CC, p_xT, p_xT, NTOK, 512, 128);
        k_ln<<<lnGrid, 256>>>(ln4_g + l*CC, ln4_b + l*CC);
        // --- ff2 ---
        k_gemm_bf<2,false><<<dim3(4, rowTiles), 256, GEMM_SMEM>>>(
            p_xn, wb + OFF_F2A, ff2_b1 + l*512, nullptr, p_ao, NTOK, 128, 512);
        k_gemm_bf<3,false><<<dim3(1, rowTiles), 256, GEMM_SMEM>>>(
            p_ao, wb + OFF_F2B, ff2_b2 + l*CC, p_xT, p_xT, NTOK, 512, 128);
        if (l == 0) k_ln<<<lnGrid, 256>>>(ln1_g + CC, ln1_b + CC);
    }
    k_tout<<<BB*TT, 256>>>((float*)d_out);
}

// round 11
// speedup vs baseline: 1.1813x; 1.0067x over previous
#include <cuda_runtime.h>
#include <cuda_bf16.h>
#include <math.h>
#include <stdint.h>

// ---------------- problem constants ----------------
#define BB     16
#define CC     128
#define TT     294
#define VV     25
#define NTOK   (BB*TT*VV)        // 117600 tokens
#define INNER  512
#define NHEAD  8
#define DH     64
#define PP     7
#define NTP    42                 // T / P
#define NKTOK  (BB*NTP*VV)        // 16800 kv tokens (global)
#define SCALE_ATT 0.125f
#define LN_EPS 1e-5f

// transposed bf16 weight layout (elements, per layer)
#define OFF_LQKV  0               // [1536,128]
#define OFF_LWO   196608          // [128,512]
#define OFF_F1A   262144          // [512,128]
#define OFF_F1B   327680          // [128,512]
#define OFF_GWQ   393216          // [512,128]
#define OFF_GWKV  458752          // [1024,896] (k reordered kp*128+c)
#define OFF_GWO   1376256         // [128,512]
#define OFF_F2A   1441792         // [512,128]
#define OFF_F2B   1507328         // [128,512]
#define WT_LSZ    1572864

// ---------------- scratch (static device memory; no allocs) ----------------
__device__ __align__(16) float          g_xT[NTOK*CC];          // residual, fp32
__device__ __align__(16) __nv_bfloat16  g_xn[NTOK*CC];          // LN output
__device__ __align__(16) __nv_bfloat16  g_qkv[(size_t)NTOK*1536];
__device__ __align__(16) __nv_bfloat16  g_q [NTOK*INNER];
__device__ __align__(16) __nv_bfloat16  g_kv[NKTOK*1024];
__device__ __align__(16) __nv_bfloat16  g_ao[NTOK*INNER];       // attn out / ff hidden
__device__ __align__(16) __nv_bfloat16  g_xg[NKTOK*896];
__device__ __align__(16) __nv_bfloat16  g_wt[2*WT_LSZ];

// ---------------- helpers ----------------
__device__ __forceinline__ uint32_t smem_u32(const void* p) {
    uint32_t a;
    asm("{ .reg .u64 t; cvta.to.shared.u64 t, %1; cvt.u32.u64 %0, t; }" : "=r"(a) : "l"(p));
    return a;
}
__device__ __forceinline__ float2 ldbf2(const __nv_bfloat16* p) {
    return __bfloat1622float2(*reinterpret_cast<const __nv_bfloat162*>(p));
}
__device__ __forceinline__ void stbf2(__nv_bfloat16* p, float2 v) {
    *reinterpret_cast<__nv_bfloat162*>(p) = __float22bfloat162_rn(v);
}
__device__ __forceinline__ float2 u2f2(uint32_t u) {
    return __bfloat1622float2(*reinterpret_cast<const __nv_bfloat162*>(&u));
}
__device__ __forceinline__ void mma_bf16(float* d, const uint32_t* a, const uint32_t* b) {
    asm volatile(
        "mma.sync.aligned.m16n8k16.row.col.f32.bf16.bf16.f32 "
        "{%0,%1,%2,%3}, {%4,%5,%6,%7}, {%8,%9}, {%0,%1,%2,%3};"
        : "+f"(d[0]), "+f"(d[1]), "+f"(d[2]), "+f"(d[3])
        : "r"(a[0]), "r"(a[1]), "r"(a[2]), "r"(a[3]), "r"(b[0]), "r"(b[1]));
}
__device__ __forceinline__ float gelu_exact(float v) {
    return 0.5f * v * (1.0f + erff(v * 0.7071067811865475f));
}

// ---------------- transpose in + fused LN(layer0,ln1) ----------------------
__global__ void k_tin(const float* __restrict__ x,
                      const float* __restrict__ gam, const float* __restrict__ bet) {
    int bt = blockIdx.x;
    int t = bt % TT, b = bt / TT;
    __shared__ float sm[CC*VV];
    for (int idx = threadIdx.x; idx < CC*VV; idx += blockDim.x) {
        int c = idx / VV, v = idx % VV;
        sm[idx] = x[(((size_t)b*CC + c)*TT + t)*VV + v];
    }
    __syncthreads();
    size_t base = ((size_t)(b*TT + t))*VV*CC;
    for (int idx = threadIdx.x; idx < CC*VV; idx += blockDim.x) {
        int v = idx / CC, c = idx % CC;
        g_xT[base + idx] = sm[c*VV + v];
    }
    int wid = threadIdx.x >> 5, lane = threadIdx.x & 31;
    int c0 = lane * 4;
    float4 gg = *(const float4*)(gam + c0);
    float4 bb = *(const float4*)(bet + c0);
    for (int v = wid; v < VV; v += 8) {
        float f0 = sm[(c0+0)*VV + v], f1 = sm[(c0+1)*VV + v];
        float f2 = sm[(c0+2)*VV + v], f3 = sm[(c0+3)*VV + v];
        float s = f0+f1+f2+f3, ss = f0*f0+f1*f1+f2*f2+f3*f3;
        #pragma unroll
        for (int o = 16; o; o >>= 1) {
            s  += __shfl_xor_sync(0xffffffffu, s,  o);
            ss += __shfl_xor_sync(0xffffffffu, ss, o);
        }
        float m = s*(1.f/128.f), var = ss*(1.f/128.f) - m*m;
        float r = rsqrtf(var + LN_EPS);
        __nv_bfloat16* dst = g_xn + base + (size_t)v*CC + c0;
        stbf2(dst,     make_float2((f0-m)*r*gg.x + bb.x, (f1-m)*r*gg.y + bb.y));
        stbf2(dst + 2, make_float2((f2-m)*r*gg.z + bb.z, (f3-m)*r*gg.w + bb.w));
    }
}

__global__ void k_tout(float* __restrict__ out) {
    int bt = blockIdx.x;
    int t = bt % TT, b = bt / TT;
    __shared__ float sm[CC*VV];
    size_t base = ((size_t)(b*TT + t))*VV*CC;
    for (int idx = threadIdx.x; idx < CC*VV; idx += blockDim.x)
        sm[idx] = g_xT[base + idx];
    __syncthreads();
    for (int idx = threadIdx.x; idx < CC*VV; idx += blockDim.x) {
        int c = idx / VV, v = idx % VV;
        out[(((size_t)b*CC + c)*TT + t)*VV + v] = sm[v*CC + c];
    }
}

// ---------------- weight prep: one launch per layer ------------------------
__global__ void k_wprep(const float* __restrict__ wq,  const float* __restrict__ wkv,
                        const float* __restrict__ wo,  const float* __restrict__ f1a,
                        const float* __restrict__ f1b, const float* __restrict__ gwq,
                        const float* __restrict__ gwkv,const float* __restrict__ gwo,
                        const float* __restrict__ f2a, const float* __restrict__ f2b,
                        __nv_bfloat16* __restrict__ dst)
{
    for (int idx = blockIdx.x*256 + threadIdx.x; idx < WT_LSZ; idx += gridDim.x*256) {
        float v;
        if (idx < OFF_LWO) {
            int m = idx >> 7, k = idx & 127;
            v = (m < 512) ? wq[k*512 + m] : wkv[k*1024 + (m-512)];
        } else if (idx < OFF_F1A) {
            int r = idx - OFF_LWO; int m = r >> 9, k = r & 511; v = wo[k*128 + m];
        } else if (idx < OFF_F1B) {
            int r = idx - OFF_F1A; int m = r >> 7, k = r & 127; v = f1a[k*512 + m];
        } else if (idx < OFF_GWQ) {
            int r = idx - OFF_F1B; int m = r >> 9, k = r & 511; v = f1b[k*128 + m];
        } else if (idx < OFF_GWKV) {
            int r = idx - OFF_GWQ; int m = r >> 7, k = r & 127; v = gwq[k*512 + m];
        } else if (idx < OFF_GWO) {
            int r = idx - OFF_GWKV; int i = r / 896; int kk = r - i*896;
            int kp = kk >> 7, c = kk & 127;
            v = gwkv[(c*PP + kp)*1024 + i];
        } else if (idx < OFF_F2A) {
            int r = idx - OFF_GWO; int m = r >> 9, k = r & 511; v = gwo[k*128 + m];
        } else if (idx < OFF_F2B) {
            int r = idx - OFF_F2A; int m = r >> 7, k = r & 127; v = f2a[k*512 + m];
        } else {
            int r = idx - OFF_F2B; int m = r >> 9, k = r & 511; v = f2b[k*128 + m];
        }
        dst[idx] = __float2bfloat16(v);
    }
}

// ---------------- bf16 mma GEMM: C[N,M] = A[N,K] @ Wt[M,K]^T ---------------
// 128x128 CTA tile, K-tile 32, 4-stage cp.async ring, ldmatrix fragments,
// swizzled row-major smem (chunk ^= (row>>1)&3). 2 CTAs/SM.
// EPI: 0 none (bf16 out), 2 bias+gelu (bf16 out), 3 bias+residual (fp32 out)
// LNF (with EPI3, M==128): phase-2 re-read of freshly written xT rows
//   (L2-hot, own-CTA writes visible after __syncthreads) -> channel LN -> xn.
#define GSTAGE_BYTES 16384
#define GEMM_SMEM   (4*GSTAGE_BYTES)

template<int EPI, bool LNF>
__global__ void __launch_bounds__(256, 2) k_gemm_bf(
    const __nv_bfloat16* __restrict__ A, const __nv_bfloat16* __restrict__ Wt,
    const float* __restrict__ bias, const float* __restrict__ res,
    void* __restrict__ Cv, __nv_bfloat16* __restrict__ xnOut,
    const float* __restrict__ gamma, const float* __restrict__ beta,
    int Nrows, int K, int M)
{
    extern __shared__ char smraw[];
    const uint32_t smb = smem_u32(smraw);

    const int t = threadIdx.x;
    const int lane = t & 31, wid = t >> 5;
    const int wr = wid & 1, wc = wid >> 1;
    const int rowBase = blockIdx.y << 7, colBase = blockIdx.x << 7;

    const int rL = t >> 1, half = t & 1;
    int ga = rowBase + rL; if (ga >= Nrows) ga = Nrows - 1;
    const __nv_bfloat16* aP = A  + (size_t)ga * K + (half << 4);
    const __nv_bfloat16* bP = Wt + (size_t)(colBase + rL) * K + (half << 4);
    const int fL = (rL >> 1) & 3;
    const uint32_t dA = rL*64 + 16*((2*half) ^ fL);
    const uint32_t dB = 8192 + dA;

    const int rA  = (lane & 7) + ((lane >> 3) & 1) * 8;
    const int ca  = lane >> 4;
    const int fra = (rA >> 1) & 3;
    const int g   = lane >> 3;
    const int nB  = ((g >> 1) & 1) * 8 + (lane & 7);
    const int cb  = g & 1;
    const int fnb = (nB >> 1) & 3;

    float acc[4][4][4];
    #pragma unroll
    for (int mt = 0; mt < 4; ++mt)
        #pragma unroll
        for (int nt = 0; nt < 4; ++nt)
            #pragma unroll
            for (int e = 0; e < 4; ++e) acc[mt][nt][e] = 0.f;

    const int nk = K >> 5;   // >= 4

    #define G_ISSUE(kt_) do {                                                   \
        const uint32_t st_ = smb + ((kt_) & 3) * GSTAGE_BYTES;                   \
        size_t sa_ = __cvta_generic_to_global(aP + ((kt_) << 5));                \
        size_t sb_ = __cvta_generic_to_global(bP + ((kt_) << 5));                \
        uint32_t a1_ = st_ + dA, b1_ = st_ + dB;                                 \
        asm volatile("cp.async.cg.shared.global [%0], [%1], 16;" :: "r"(a1_), "l"(sa_)); \
        asm volatile("cp.async.cg.shared.global [%0], [%1], 16;" :: "r"(a1_ ^ 16u), "l"(sa_ + 16)); \
        asm volatile("cp.async.cg.shared.global [%0], [%1], 16;" :: "r"(b1_), "l"(sb_)); \
        asm volatile("cp.async.cg.shared.global [%0], [%1], 16;" :: "r"(b1_ ^ 16u), "l"(sb_ + 16)); \
    } while (0)

    G_ISSUE(0); asm volatile("cp.async.commit_group;");
    G_ISSUE(1); asm volatile("cp.async.commit_group;");
    G_ISSUE(2); asm volatile("cp.async.commit_group;");

    for (int kt = 0; kt < nk; ++kt) {
        asm volatile("cp.async.wait_group 2;");
        __syncthreads();
        if (kt + 3 < nk) G_ISSUE(kt + 3);
        asm volatile("cp.async.commit_group;");

        const uint32_t stA = smb + (kt & 3) * GSTAGE_BYTES;
        const uint32_t stB = stA + 8192;
        #pragma unroll
        for (int ks = 0; ks < 2; ++ks) {
            uint32_t af[4][4], bf[4][2];
            #pragma unroll
            for (int mt = 0; mt < 4; ++mt) {
                uint32_t addr = stA + (uint32_t)((wr*64 + mt*16 + rA)*64)
                              + 16u*(uint32_t)(((ks<<1) + ca) ^ fra);
                asm volatile("ldmatrix.sync.aligned.m8n8.x4.shared.b16 {%0,%1,%2,%3}, [%4];"
                    : "=r"(af[mt][0]), "=r"(af[mt][1]), "=r"(af[mt][2]), "=r"(af[mt][3])
                    : "r"(addr));
            }
            #pragma unroll
            for (int j = 0; j < 2; ++j) {
                int n = wc*32 + j*16 + nB;
                uint32_t addr = stB + (uint32_t)(n*64)
                              + 16u*(uint32_t)(((ks<<1) + cb) ^ fnb);
                asm volatile("ldmatrix.sync.aligned.m8n8.x4.shared.b16 {%0,%1,%2,%3}, [%4];"
                    : "=r"(bf[2*j][0]), "=r"(bf[2*j][1]), "=r"(bf[2*j+1][0]), "=r"(bf[2*j+1][1])
                    : "r"(addr));
            }
            #pragma unroll
            for (int mt = 0; mt < 4; ++mt)
                #pragma unroll
                for (int nt = 0; nt < 4; ++nt)
                    mma_bf16(acc[mt][nt], af[mt], bf[nt]);
        }
    }
    #undef G_ISSUE

    // ---------------- epilogue phase 1 ----------------
    #pragma unroll
    for (int nt = 0; nt < 4; ++nt) {
        const int col = colBase + wc*32 + nt*8 + (lane & 3)*2;
        float2 bb = make_float2(0.f, 0.f);
        if (EPI >= 1) bb = *(const float2*)(bias + col);
        #pragma unroll
        for (int mt = 0; mt < 4; ++mt) {
            #pragma unroll
            for (int hf = 0; hf < 2; ++hf) {
                const int r = rowBase + wr*64 + mt*16 + (lane >> 2) + hf*8;
                if (r >= Nrows) continue;
                float2 o = make_float2(acc[mt][nt][hf*2+0] + bb.x,
                                       acc[mt][nt][hf*2+1] + bb.y);
                if (EPI == 2) { o.x = gelu_exact(o.x); o.y = gelu_exact(o.y); }
                if (EPI == 3) {
                    float2 rv = *(const float2*)(res + (size_t)r*M + col);
                    o.x += rv.x; o.y += rv.y;
                    *(float2*)((float*)Cv + (size_t)r*M + col) = o;
                } else {
                    stbf2((__nv_bfloat16*)Cv + (size_t)r*M + col, o);
                }
            }
        }
    }

    // ---------------- epilogue phase 2: fused LN via L2 re-read -------------
    if (LNF) {
        __syncthreads();   // own-CTA global writes now visible block-wide
        const float* xTp = (const float*)Cv;
        int c0 = lane * 4;
        float4 gg = *(const float4*)(gamma + c0);
        float4 bb = *(const float4*)(beta + c0);
        for (int rr = wid; rr < 128; rr += 8) {
            int r = rowBase + rr;
            if (r >= Nrows) break;
            float4 a = ((const float4*)(xTp + (size_t)r*128))[lane];
            float s  = a.x + a.y + a.z + a.w;
            float ss = a.x*a.x + a.y*a.y + a.z*a.z + a.w*a.w;
            #pragma unroll
            for (int o = 16; o; o >>= 1) {
                s  += __shfl_xor_sync(0xffffffffu, s,  o);
                ss += __shfl_xor_sync(0xffffffffu, ss, o);
            }
            float m   = s * (1.f/128.f);
            float var = ss * (1.f/128.f) - m*m;
            float rv  = rsqrtf(var + LN_EPS);
            __nv_bfloat16* dst = xnOut + (size_t)r*128 + c0;
            stbf2(dst,     make_float2((a.x-m)*rv*gg.x + bb.x, (a.y-m)*rv*gg.y + bb.y));
            stbf2(dst + 2, make_float2((a.z-m)*rv*gg.z + bb.z, (a.w-m)*rv*gg.w + bb.w));
        }
    }
}

// ---------------- local attention: one warp per (b, patch, v, head) --------
__global__ void __launch_bounds__(256) k_lattn() {
    int w = blockIdx.x * 8 + (threadIdx.x >> 5);
    int lane = threadIdx.x & 31;
    int h = w & 7;
    int g = w >> 3;
    int v = g % VV;
    int r = g / VV;
    int tt = r % NTP;
    int b = r / NTP;
    int d0 = lane * 2;

    float2 q[PP], kk[PP], vv[PP];
    #pragma unroll
    for (int p = 0; p < PP; ++p) {
        int n = (b*TT + tt*PP + p)*VV + v;
        const __nv_bfloat16* rowp = g_qkv + (size_t)n*1536 + h*DH + d0;
        q[p]  = ldbf2(rowp);
        kk[p] = ldbf2(rowp + 512);
        vv[p] = ldbf2(rowp + 1024);
    }
    float dots[PP][PP];
    #pragma unroll
    for (int i = 0; i < PP; ++i)
        #pragma unroll
        for (int j = 0; j < PP; ++j)
            dots[i][j] = q[i].x*kk[j].x + q[i].y*kk[j].y;
    #pragma unroll
    for (int o = 16; o; o >>= 1)
        #pragma unroll
        for (int i = 0; i < PP; ++i)
            #pragma unroll
            for (int j = 0; j < PP; ++j)
                dots[i][j] += __shfl_xor_sync(0xffffffffu, dots[i][j], o);
    #pragma unroll
    for (int i = 0; i < PP; ++i) {
        float mx = -1e30f;
        #pragma unroll
        for (int j = 0; j < PP; ++j) {
            dots[i][j] *= SCALE_ATT;
            mx = fmaxf(mx, dots[i][j]);
        }
        float s = 0.f;
        #pragma unroll
        for (int j = 0; j < PP; ++j) { dots[i][j] = __expf(dots[i][j] - mx); s += dots[i][j]; }
        float inv = 1.f / s;
        #pragma unroll
        for (int j = 0; j < PP; ++j) dots[i][j] *= inv;
    }
    #pragma unroll
    for (int i = 0; i < PP; ++i) {
        float2 o = make_float2(0.f, 0.f);
        #pragma unroll
        for (int j = 0; j < PP; ++j) {
            o.x += dots[i][j] * vv[j].x;
            o.y += dots[i][j] * vv[j].y;
        }
        int n = (b*TT + tt*PP + i)*VV + v;
        stbf2(g_ao + (size_t)n*INNER + h*DH + d0, o);
    }
}

// ---------------- gather (coalesced row copies) -----------------------------
__global__ void k_gather() {
    int idx = blockIdx.x * 256 + threadIdx.x;     // over NKTOK * 7 * 16 (uint4 of 8 bf16)
    if (idx >= NKTOK*112) return;
    int nk = idx / 112;
    int rem = idx - nk*112;
    int kp = rem >> 4, u = rem & 15;
    int v  = nk % VV;
    int rr = nk / VV;
    int tt = rr % NTP;
    int b  = rr / NTP;
    int src = ((b*TT + tt*PP + kp)*VV + v)*CC + u*8;
    *reinterpret_cast<uint4*>(g_xg + (size_t)nk*896 + kp*128 + u*8) =
        *reinterpret_cast<const uint4*>(g_xn + src);
}

// ---------------- global attention: one block per (b, h, v) ----------------
__global__ void __launch_bounds__(160) k_gattn() {
    int bid = blockIdx.x;
    int v = bid % VV;
    int rr = bid / VV;
    int h = rr & 7;
    int b = rr >> 3;
    __shared__ float ks[NTP][DH];
    __shared__ float vs[NTP][DH];
    for (int idx = threadIdx.x; idx < NTP*DH/2; idx += 160) {
        int j = idx >> 5, d2 = idx & 31;
        int nk = (b*NTP + j)*VV + v;
        size_t o = (size_t)nk*1024 + h*DH + d2*2;
        float2 kf = ldbf2(g_kv + o);
        float2 vf = ldbf2(g_kv + o + 512);
        ks[j][d2*2] = kf.x; ks[j][d2*2+1] = kf.y;
        vs[j][d2*2] = vf.x; vs[j][d2*2+1] = vf.y;
    }
    __syncthreads();
    int tid = threadIdx.x;
    if (tid >= 147) return;
    int i0 = 2*tid;
    size_t q0 = (size_t)((b*TT + i0)*VV + v)*INNER + h*DH;
    size_t q1 = q0 + (size_t)VV*INNER;

    float da[NTP], db[NTP];
    #pragma unroll
    for (int j = 0; j < NTP; ++j) { da[j] = 0.f; db[j] = 0.f; }

    for (int dchunk = 0; dchunk < 4; ++dchunk) {
        int dbase = dchunk * 16;
        float qa[16], qb[16];
        {
            uint4 u0 = *(const uint4*)(g_q + q0 + dbase);
            uint4 u1 = *(const uint4*)(g_q + q0 + dbase + 8);
            uint4 w0 = *(const uint4*)(g_q + q1 + dbase);
            uint4 w1 = *(const uint4*)(g_q + q1 + dbase + 8);
            float2 f;
            f=u2f2(u0.x); qa[0]=f.x; qa[1]=f.y;  f=u2f2(u0.y); qa[2]=f.x; qa[3]=f.y;
            f=u2f2(u0.z); qa[4]=f.x; qa[5]=f.y;  f=u2f2(u0.w); qa[6]=f.x; qa[7]=f.y;
            f=u2f2(u1.x); qa[8]=f.x; qa[9]=f.y;  f=u2f2(u1.y); qa[10]=f.x; qa[11]=f.y;
            f=u2f2(u1.z); qa[12]=f.x; qa[13]=f.y; f=u2f2(u1.w); qa[14]=f.x; qa[15]=f.y;
            f=u2f2(w0.x); qb[0]=f.x; qb[1]=f.y;  f=u2f2(w0.y); qb[2]=f.x; qb[3]=f.y;
            f=u2f2(w0.z); qb[4]=f.x; qb[5]=f.y;  f=u2f2(w0.w); qb[6]=f.x; qb[7]=f.y;
            f=u2f2(w1.x); qb[8]=f.x; qb[9]=f.y;  f=u2f2(w1.y); qb[10]=f.x; qb[11]=f.y;
            f=u2f2(w1.z); qb[12]=f.x; qb[13]=f.y; f=u2f2(w1.w); qb[14]=f.x; qb[15]=f.y;
        }
        #pragma unroll
        for (int j = 0; j < NTP; ++j) {
            #pragma unroll
            for (int dd = 0; dd < 16; ++dd) {
                float kv = ks[j][dbase + dd];
                da[j] += qa[dd] * kv;
                db[j] += qb[dd] * kv;
            }
        }
    }
    {
        float mx = -1e30f;
        #pragma unroll
        for (int j = 0; j < NTP; ++j) { da[j] *= SCALE_ATT; mx = fmaxf(mx, da[j]); }
        float s = 0.f;
        #pragma unroll
        for (int j = 0; j < NTP; ++j) { da[j] = __expf(da[j] - mx); s += da[j]; }
        float inv = 1.f / s;
        #pragma unroll
        for (int j = 0; j < NTP; ++j) da[j] *= inv;
    }
    {
        float mx = -1e30f;
        #pragma unroll
        for (int j = 0; j < NTP; ++j) { db[j] *= SCALE_ATT; mx = fmaxf(mx, db[j]); }
        float s = 0.f;
        #pragma unroll
        for (int j = 0; j < NTP; ++j) { db[j] = __expf(db[j] - mx); s += db[j]; }
        float inv = 1.f / s;
        #pragma unroll
        for (int j = 0; j < NTP; ++j) db[j] *= inv;
    }
    size_t o0 = q0, o1 = q1;
    for (int dchunk = 0; dchunk < 4; ++dchunk) {
        int dbase = dchunk * 16;
        float oa[16], ob[16];
        #pragma unroll
        for (int dd = 0; dd < 16; ++dd) { oa[dd] = 0.f; ob[dd] = 0.f; }
        #pragma unroll
        for (int j = 0; j < NTP; ++j) {
            #pragma unroll
            for (int dd = 0; dd < 16; ++dd) {
                float vv = vs[j][dbase + dd];
                oa[dd] += da[j] * vv;
                ob[dd] += db[j] * vv;
            }
        }
        #pragma unroll
        for (int dd = 0; dd < 16; dd += 2) {
            stbf2(g_ao + o0 + dbase + dd, make_float2(oa[dd], oa[dd+1]));
            stbf2(g_ao + o1 + dbase + dd, make_float2(ob[dd], ob[dd+1]));
        }
    }
}

// ---------------- launch -----------------------------------------------------
extern "C" void kernel_launch(void* const* d_in, const int* in_sizes, int n_in,
                              void* d_out, int out_size) {
    (void)in_sizes; (void)n_in; (void)out_size;
    float* p_xT;
    __nv_bfloat16 *p_xn, *p_qkv, *p_q, *p_kv, *p_ao, *p_xg, *p_wt;
    cudaGetSymbolAddress((void**)&p_xT,  g_xT);
    cudaGetSymbolAddress((void**)&p_xn,  g_xn);
    cudaGetSymbolAddress((void**)&p_qkv, g_qkv);
    cudaGetSymbolAddress((void**)&p_q,   g_q);
    cudaGetSymbolAddress((void**)&p_kv,  g_kv);
    cudaGetSymbolAddress((void**)&p_ao,  g_ao);
    cudaGetSymbolAddress((void**)&p_xg,  g_xg);
    cudaGetSymbolAddress((void**)&p_wt,  g_wt);

    cudaFuncSetAttribute((k_gemm_bf<0,false>), cudaFuncAttributeMaxDynamicSharedMemorySize, GEMM_SMEM);
    cudaFuncSetAttribute((k_gemm_bf<2,false>), cudaFuncAttributeMaxDynamicSharedMemorySize, GEMM_SMEM);
    cudaFuncSetAttribute((k_gemm_bf<3,true>),  cudaFuncAttributeMaxDynamicSharedMemorySize, GEMM_SMEM);
    cudaFuncSetAttribute((k_gemm_bf<3,false>), cudaFuncAttributeMaxDynamicSharedMemorySize, GEMM_SMEM);

    const float* x      = (const float*)d_in[0];
    const float* ln1_g  = (const float*)d_in[1];
    const float* ln1_b  = (const float*)d_in[2];
    const float* la_wq  = (const float*)d_in[3];
    const float* la_wkv = (const float*)d_in[4];
    const float* la_wo  = (const float*)d_in[5];
    const float* la_bo  = (const float*)d_in[6];
    const float* ln2_g  = (const float*)d_in[7];
    const float* ln2_b  = (const float*)d_in[8];
    const float* ff1_w1 = (const float*)d_in[9];
    const float* ff1_b1 = (const float*)d_in[10];
    const float* ff1_w2 = (const float*)d_in[11];
    const float* ff1_b2 = (const float*)d_in[12];
    const float* ln3_g  = (const float*)d_in[13];
    const float* ln3_b  = (const float*)d_in[14];
    const float* ga_wq  = (const float*)d_in[15];
    const float* ga_wkv = (const float*)d_in[16];
    const float* ga_wo  = (const float*)d_in[17];
    const float* ga_bo  = (const float*)d_in[18];
    const float* ln4_g  = (const float*)d_in[19];
    const float* ln4_b  = (const float*)d_in[20];
    const float* ff2_w1 = (const float*)d_in[21];
    const float* ff2_b1 = (const float*)d_in[22];
    const float* ff2_w2 = (const float*)d_in[23];
    const float* ff2_b2 = (const float*)d_in[24];

    for (int l = 0; l < 2; ++l) {
        k_wprep<<<4096, 256>>>(
            la_wq  + (size_t)l*CC*INNER,      la_wkv + (size_t)l*CC*2*INNER,
            la_wo  + (size_t)l*INNER*CC,      ff1_w1 + (size_t)l*CC*512,
            ff1_w2 + (size_t)l*512*CC,        ga_wq  + (size_t)l*CC*INNER,
            ga_wkv + (size_t)l*CC*PP*2*INNER, ga_wo  + (size_t)l*INNER*CC,
            ff2_w1 + (size_t)l*CC*512,        ff2_w2 + (size_t)l*512*CC,
            p_wt + (size_t)l*WT_LSZ);
    }

    const int rowTiles  = (NTOK  + 127) / 128;   // 919
    const int rowTilesG = (NKTOK + 127) / 128;   // 132

    k_tin<<<BB*TT, 256>>>(x, ln1_g, ln1_b);

    for (int l = 0; l < 2; ++l) {
        __nv_bfloat16* wb = p_wt + (size_t)l*WT_LSZ;
        // --- local attention block ---
        k_gemm_bf<0,false><<<dim3(12, rowTiles), 256, GEMM_SMEM>>>(
            p_xn, wb + OFF_LQKV, nullptr, nullptr, p_qkv, nullptr, nullptr, nullptr, NTOK, 128, 1536);
        k_lattn<<<NKTOK, 256>>>();
        k_gemm_bf<3,true><<<dim3(1, rowTiles), 256, GEMM_SMEM>>>(
            p_ao, wb + OFF_LWO, la_bo + l*CC, p_xT, p_xT, p_xn, ln2_g + l*CC, ln2_b + l*CC, NTOK, 512, 128);
        // --- ff1 ---
        k_gemm_bf<2,false><<<dim3(4, rowTiles), 256, GEMM_SMEM>>>(
            p_xn, wb + OFF_F1A, ff1_b1 + l*512, nullptr, p_ao, nullptr, nullptr, nullptr, NTOK, 128, 512);
        k_gemm_bf<3,true><<<dim3(1, rowTiles), 256, GEMM_SMEM>>>(
            p_ao, wb + OFF_F1B, ff1_b2 + l*CC, p_xT, p_xT, p_xn, ln3_g + l*CC, ln3_b + l*CC, NTOK, 512, 128);
        // --- global attention block ---
        k_gemm_bf<0,false><<<dim3(4, rowTiles), 256, GEMM_SMEM>>>(
            p_xn, wb + OFF_GWQ, nullptr, nullptr, p_q, nullptr, nullptr, nullptr, NTOK, 128, 512);
        k_gather<<<(NKTOK*112 + 255)/256, 256>>>();
        k_gemm_bf<0,false><<<dim3(8, rowTilesG), 256, GEMM_SMEM>>>(
            p_xg, wb + OFF_GWKV, nullptr, nullptr, p_kv, nullptr, nullptr, nullptr, NKTOK, 896, 1024);
        k_gattn<<<BB*NHEAD*VV, 160>>>();
        k_gemm_bf<3,true><<<dim3(1, rowTiles), 256, GEMM_SMEM>>>(
            p_ao, wb + OFF_GWO, ga_bo + l*CC, p_xT, p_xT, p_xn, ln4_g + l*CC, ln4_b + l*CC, NTOK, 512, 128);
        // --- ff2 ---
        k_gemm_bf<2,false><<<dim3(4, rowTiles), 256, GEMM_SMEM>>>(
            p_xn, wb + OFF_F2A, ff2_b1 + l*512, nullptr, p_ao, nullptr, nullptr, nullptr, NTOK, 128, 512);
        if (l == 0) {
            k_gemm_bf<3,true><<<dim3(1, rowTiles), 256, GEMM_SMEM>>>(
                p_ao, wb + OFF_F2B, ff2_b2 + l*CC, p_xT, p_xT, p_xn, ln1_g + CC, ln1_b + CC, NTOK, 512, 128);
        } else {
            k_gemm_bf<3,false><<<dim3(1, rowTiles), 256, GEMM_SMEM>>>(
                p_ao, wb + OFF_F2B, ff2_b2 + l*CC, p_xT, p_xT, nullptr, nullptr, nullptr, NTOK, 512, 128);
        }
    }
    k_tout<<<BB*TT, 256>>>((float*)d_out);
}